// round 13
// baseline (speedup 1.0000x reference)
#include <cuda_runtime.h>
#include <math_constants.h>

// Hausdorff loss: x,y (8, 4096, 3) fp32 -> scalar, ONE kernel launch.
// |q-t|^2 = |q|^2 + (|t|^2 - 2 q.t); min/max on squared values, sqrt at end.
//
// Decomposition: work unit (dir, b, target-chunk), 2*8*37 = 592 CTAs = 4/SM
// (148*4), one wave. Each CTA scans all 4096 queries (4/thread, 4 passes)
// against its target chunk in smem.
//
// KEY CHANGE (R13): chunks padded to a COMPILE-TIME 112 targets with sentinel
// (0,0,0,+INF) -> constant trip count, unroll 8 divides evenly (112 = 8*14),
// no guarded remainder loop, clean LDS software pipelining. Sentinel yields
// v = INF which fminf ignores (no NaN path).
//
// Complement-bits merge: for s >= 0, min(bits) == ~max(~bits), identity 0
// ==> zero-initialized __device__ scratch, no init kernel, replay-safe.
// Per-slab last-done CTA reduces + restores its slab; global last-done CTA
// emits the scalar and resets all state.

#define NB 8
#define V  4096
#define TC 37                         // 2*8*37 = 592 CTAs = 148*4
#define THREADS 256
#define QPT 4                         // queries per thread per pass
#define NPASS (V / (QPT * THREADS))   // 4
#define NTP 112                       // padded chunk size (compile-time trips)
#define NSLAB (2 * NB)                // 16
#define NWARP (THREADS / 32)

__device__ unsigned g_comp[NSLAB * V];    // zero-init == identity for max(~bits)
__device__ unsigned g_max[NB];
__device__ unsigned g_slab_done[NSLAB];
__device__ unsigned g_done;

__global__ void __launch_bounds__(THREADS, 4)
hd_main_kernel(const float* __restrict__ X, const float* __restrict__ Y,
               float* __restrict__ out) {
    __shared__ float4 sT[NTP];
    __shared__ float wmax[NWARP];
    __shared__ int s_role;

    const int tc  = blockIdx.x;          // 0..36
    const int b   = blockIdx.y;
    const int dir = blockIdx.z;
    const int slab_id = dir * NB + b;
    const float* __restrict__ Qp = (dir == 0 ? X : Y) + (size_t)b * V * 3;
    const float* __restrict__ Tp = (dir == 0 ? Y : X) + (size_t)b * V * 3;
    unsigned* __restrict__ slab = g_comp + (size_t)slab_id * V;

    const int t0 = (tc * V) / TC;
    const int nt = ((tc + 1) * V) / TC - t0;   // 110 or 111
    const int tid = threadIdx.x;
    const int wid = tid >> 5;
    const int lid = tid & 31;

    // Stage targets (x, y, z, |t|^2); pad [nt, NTP) with (0,0,0,+INF).
    if (tid < NTP) {
        float4 v = make_float4(0.0f, 0.0f, 0.0f, CUDART_INF_F);
        if (tid < nt) {
            const int g = t0 + tid;
            const float tx = Tp[g * 3 + 0];
            const float ty = Tp[g * 3 + 1];
            const float tz = Tp[g * 3 + 2];
            v = make_float4(tx, ty, tz, tx * tx + ty * ty + tz * tz);
        }
        sT[tid] = v;
    }
    __syncthreads();

    #pragma unroll 1
    for (int p = 0; p < NPASS; p++) {
        const int qb = p * (QPT * THREADS) + tid;

        float ax[QPT], ay[QPT], az[QPT], m[QPT];
        #pragma unroll
        for (int k = 0; k < QPT; k++) {
            const int q = qb + k * THREADS;
            ax[k] = -2.0f * Qp[q * 3 + 0];
            ay[k] = -2.0f * Qp[q * 3 + 1];
            az[k] = -2.0f * Qp[q * 3 + 2];
            m[k]  = CUDART_INF_F;
        }

        #pragma unroll 8
        for (int j = 0; j < NTP; j++) {      // constant trips, even unroll
            const float4 t = sT[j];          // broadcast LDS.128
            #pragma unroll
            for (int k = 0; k < QPT; k++) {
                const float v = fmaf(ax[k], t.x,
                                fmaf(ay[k], t.y,
                                fmaf(az[k], t.z, t.w)));
                m[k] = fminf(m[k], v);
            }
        }

        #pragma unroll
        for (int k = 0; k < QPT; k++) {
            // |q|^2 = 0.25 * (ax^2 + ay^2 + az^2)  (recomputed; saves regs)
            const float q2 = 0.25f * fmaf(ax[k], ax[k],
                                     fmaf(ay[k], ay[k], az[k] * az[k]));
            const float s = fmaxf(q2 + m[k], 0.0f);
            // min over chunks == ~(max over chunks of ~bits); identity 0.
            atomicMax(&slab[qb + k * THREADS], ~__float_as_uint(s));
        }
    }

    // ---- per-slab last-done CTA reduces its slab (parallel, overlapped) ----
    __threadfence();
    __syncthreads();
    if (tid == 0)
        s_role = (atomicAdd(&g_slab_done[slab_id], 1u) == TC - 1);
    __syncthreads();
    if (!s_role) return;

    __threadfence();   // acquire: all 37 chunk CTAs' atomics visible

    float mm = 0.0f;
    {   // 4096 words, 256 threads, uint4-vectorized.
        uint4* __restrict__ slab4 = reinterpret_cast<uint4*>(slab);
        #pragma unroll
        for (int i = tid; i < V / 4; i += THREADS) {
            const uint4 w = slab4[i];
            mm = fmaxf(mm, __uint_as_float(~w.x));
            mm = fmaxf(mm, __uint_as_float(~w.y));
            mm = fmaxf(mm, __uint_as_float(~w.z));
            mm = fmaxf(mm, __uint_as_float(~w.w));
            slab4[i] = make_uint4(0u, 0u, 0u, 0u);   // restore identity
        }
    }
    #pragma unroll
    for (int off = 16; off > 0; off >>= 1)
        mm = fmaxf(mm, __shfl_xor_sync(0xffffffffu, mm, off));
    if (lid == 0) wmax[wid] = mm;
    __syncthreads();

    if (tid == 0) {
        float mx = wmax[0];
        #pragma unroll
        for (int w = 1; w < NWARP; w++) mx = fmaxf(mx, wmax[w]);
        atomicMax(&g_max[b], __float_as_uint(mx));   // nonneg bits
        g_slab_done[slab_id] = 0u;                   // restore (all 37 arrived)

        __threadfence();
        if (atomicAdd(&g_done, 1u) == NSLAB - 1) {   // global last: finalize
            __threadfence();
            float s = 0.0f;
            #pragma unroll
            for (int i = 0; i < NB; i++) {
                s += sqrtf(__uint_as_float(g_max[i]));
                g_max[i] = 0u;                       // restore
            }
            out[0] = s * (1.0f / (float)NB);         // LOSS_WEIGHT = 1.0
            g_done = 0u;                             // restore
        }
    }
}

extern "C" void kernel_launch(void* const* d_in, const int* in_sizes, int n_in,
                              void* d_out, int out_size) {
    const float* x = (const float*)d_in[0];
    const float* y = (const float*)d_in[1];
    float* out = (float*)d_out;

    dim3 grid(TC, NB, 2);
    hd_main_kernel<<<grid, THREADS>>>(x, y, out);
}